// round 15
// baseline (speedup 1.0000x reference)
#include <cuda_runtime.h>
#include <cuda_fp16.h>
#include <cstdint>
#include <math.h>

// Problem constants
#define BATCH 4
#define SQ    2048
#define SKV   2048
#define E     1024
#define H     8
#define HD    128

// ---------------------------------------------------------------------------
// Scratch (__device__ globals; referenced ONLY from device code)
// ---------------------------------------------------------------------------
__device__ __half g_ah[(size_t)BATCH * SQ * E];    // q activation fp16
__device__ __half g_bh[(size_t)BATCH * SKV * E];   // v activation fp16
__device__ __half g_wth[3][(size_t)E * E];         // (W^T * 32) fp16
// Projection outputs, plain fp16 (sigma~1)
__device__ __half g_qp[(size_t)BATCH * SQ * E];
__device__ __half g_kp[(size_t)BATCH * SKV * E];
__device__ __half g_vp[(size_t)BATCH * SKV * E];

// ---------------------------------------------------------------------------
// Helpers
// ---------------------------------------------------------------------------
__device__ __forceinline__ uint32_t smem_to_u32(const void* p) {
    uint32_t a;
    asm("{ .reg .u64 t; cvta.to.shared.u64 t, %1; cvt.u32.u64 %0, t; }"
        : "=r"(a) : "l"(p));
    return a;
}

#define CP_ASYNC_16(dst, src) \
    asm volatile("cp.async.cg.shared.global [%0], [%1], 16;" :: "r"(dst), "l"(src))
#define CP_COMMIT() asm volatile("cp.async.commit_group;" ::: "memory")
template <int N>
__device__ __forceinline__ void cp_wait() {
    asm volatile("cp.async.wait_group %0;" :: "n"(N) : "memory");
}

#define LDMATRIX_X4(r0, r1, r2, r3, addr) \
    asm volatile("ldmatrix.sync.aligned.m8n8.x4.shared.b16 {%0,%1,%2,%3}, [%4];" \
        : "=r"(r0), "=r"(r1), "=r"(r2), "=r"(r3) : "r"(addr))
#define LDMATRIX_X4_T(r0, r1, r2, r3, addr) \
    asm volatile("ldmatrix.sync.aligned.m8n8.x4.trans.shared.b16 {%0,%1,%2,%3}, [%4];" \
        : "=r"(r0), "=r"(r1), "=r"(r2), "=r"(r3) : "r"(addr))

#define MMA_F16(c, a, b0, b1) \
    asm volatile("mma.sync.aligned.m16n8k16.row.col.f32.f16.f16.f32 " \
        "{%0,%1,%2,%3}, {%4,%5,%6,%7}, {%8,%9}, {%0,%1,%2,%3};" \
        : "+f"((c)[0]), "+f"((c)[1]), "+f"((c)[2]), "+f"((c)[3]) \
        : "r"((a)[0]), "r"((a)[1]), "r"((a)[2]), "r"((a)[3]), "r"(b0), "r"(b1))

__device__ __forceinline__ uint32_t pack_f16(float lo, float hi) {
    uint32_t d;
    asm("cvt.rn.f16x2.f32 %0, %1, %2;" : "=r"(d) : "f"(hi), "f"(lo));
    return d;
}

// ---------------------------------------------------------------------------
// Conversion: activations -> plain fp16
// ---------------------------------------------------------------------------
__global__ __launch_bounds__(256) void conv_act(const float* __restrict__ q,
                                                const float* __restrict__ v)
{
    size_t t = (size_t)blockIdx.x * 256 + threadIdx.x;
    const float* src = blockIdx.y ? v : q;
    __half* hi = blockIdx.y ? g_bh : g_ah;
    float4 x = *(const float4*)(src + t * 4);
    __half2* hp = reinterpret_cast<__half2*>(hi + t * 4);
    hp[0] = {__float2half_rn(x.x), __float2half_rn(x.y)};
    hp[1] = {__float2half_rn(x.z), __float2half_rn(x.w)};
}

// W -> (W^T * 32) fp16
__global__ __launch_bounds__(256) void conv_w(const float* __restrict__ Wq,
                                              const float* __restrict__ Wk,
                                              const float* __restrict__ Wv)
{
    __shared__ float ts[32][33];
    const int z = blockIdx.z;
    const float* W = (z == 0) ? Wq : (z == 1) ? Wk : Wv;
    __half* hi = g_wth[z];
    const int tx = threadIdx.x, ty = threadIdx.y;
    const int n0 = blockIdx.x * 32, k0 = blockIdx.y * 32;
#pragma unroll
    for (int i = 0; i < 32; i += 8)
        ts[ty + i][tx] = W[(size_t)(k0 + ty + i) * E + n0 + tx];
    __syncthreads();
#pragma unroll
    for (int i = 0; i < 32; i += 8) {
        float x = ts[tx][ty + i] * 32.0f;
        hi[(size_t)(n0 + ty + i) * E + k0 + tx] = __float2half_rn(x);
    }
}

// ---------------------------------------------------------------------------
// fp16 projection GEMM (unchanged from R13 — RF-frozen at 128 regs/thread):
//   C = round16(A·Wh/32 + bias), K-chunk 64, 3-stage ring, 1 barrier/chunk.
// ---------------------------------------------------------------------------
#define KC64 64
#define ROWB64 144
#define TILE64_B (128 * ROWB64)
#define G_STAGE3 (2 * TILE64_B)

__global__ __launch_bounds__(256, 2) void gemm_mma(
    const float* __restrict__ bq, const float* __restrict__ bk,
    const float* __restrict__ bv)
{
    const int z = blockIdx.z;
    const __half* A   = (z == 0) ? g_ah : g_bh;
    const __half* Bh_ = g_wth[z];
    const float* bias = (z == 0) ? bq : (z == 1) ? bk : bv;
    __half* C         = (z == 0) ? g_qp : (z == 1) ? g_kp : g_vp;

    const int mBase = blockIdx.y * 128;
    const int nBase = blockIdx.x * 128;
    const int tid  = threadIdx.x;
    const int wid  = tid >> 5;
    const int lane = tid & 31;
    const int m0 = (wid >> 1) * 32;
    const int n0 = (wid & 1) * 64;

    extern __shared__ char smraw[];
    const uint32_t sb = smem_to_u32(smraw);

    auto issue_loads = [&](int c, int s) {
        const int k0 = c * KC64;
        const uint32_t base = sb + s * G_STAGE3;
#pragma unroll
        for (int t = 0; t < 8; t++) {
            int flat = tid + t * 256;
            int tile = flat >> 10;
            int idx  = flat & 1023;
            int row  = idx >> 3;
            int ch   = idx & 7;
            uint32_t dst = base + tile * TILE64_B + row * ROWB64 + ch * 16;
            const __half* src = (tile == 0)
                ? A   + (size_t)(mBase + row) * E + k0 + ch * 8
                : Bh_ + (size_t)(nBase + row) * E + k0 + ch * 8;
            CP_ASYNC_16(dst, src);
        }
        CP_COMMIT();
    };

    float c[2][8][4];
#pragma unroll
    for (int i = 0; i < 2; i++)
#pragma unroll
        for (int j = 0; j < 8; j++)
#pragma unroll
            for (int r = 0; r < 4; r++) c[i][j][r] = 0.f;

    issue_loads(0, 0);
    issue_loads(1, 1);

    const int aRow = lane & 15;
    const int aKk  = (lane >> 4) << 3;
    const int bRow = (lane & 7) + ((lane >> 4) << 3);
    const int bKk  = ((lane >> 3) & 1) << 3;

    const int NCH = E / KC64;
    for (int cidx = 0; cidx < NCH; cidx++) {
        const int s = cidx % 3;
        if (cidx < NCH - 1) cp_wait<1>(); else cp_wait<0>();
        __syncthreads();
        if (cidx + 2 < NCH) issue_loads(cidx + 2, (cidx + 2) % 3);

        const uint32_t AB  = sb + s * G_STAGE3;
        const uint32_t BhB = AB + TILE64_B;

#pragma unroll
        for (int ks = 0; ks < KC64; ks += 16) {
            uint32_t ah[2][4];
#pragma unroll
            for (int mb = 0; mb < 2; mb++) {
                uint32_t adr = AB + (m0 + mb * 16 + aRow) * ROWB64 + (ks + aKk) * 2;
                LDMATRIX_X4(ah[mb][0], ah[mb][1], ah[mb][2], ah[mb][3], adr);
            }
#pragma unroll
            for (int half = 0; half < 2; half++) {
                uint32_t bh[2][4];
#pragma unroll
                for (int nbi = 0; nbi < 2; nbi++) {
                    int nb = half * 2 + nbi;
                    uint32_t adr = BhB + (n0 + nb * 16 + bRow) * ROWB64 + (ks + bKk) * 2;
                    LDMATRIX_X4(bh[nbi][0], bh[nbi][1], bh[nbi][2], bh[nbi][3], adr);
                }
#pragma unroll
                for (int mb = 0; mb < 2; mb++)
#pragma unroll
                    for (int nbi = 0; nbi < 2; nbi++) {
                        int j = (half * 2 + nbi) * 2;
                        MMA_F16(c[mb][j],     ah[mb], bh[nbi][0], bh[nbi][1]);
                        MMA_F16(c[mb][j + 1], ah[mb], bh[nbi][2], bh[nbi][3]);
                    }
            }
        }
    }

    const int rw = lane >> 2;
    const int cw = (lane & 3) * 2;
#pragma unroll
    for (int mb = 0; mb < 2; mb++) {
        int row0 = mBase + m0 + mb * 16 + rw;
#pragma unroll
        for (int j = 0; j < 8; j++) {
            int col = nBase + n0 + j * 8 + cw;
            float2 bb = *(const float2*)(bias + col);
            float x0 = fmaf(c[mb][j][0], 0.03125f, bb.x);
            float x1 = fmaf(c[mb][j][1], 0.03125f, bb.y);
            float x2 = fmaf(c[mb][j][2], 0.03125f, bb.x);
            float x3 = fmaf(c[mb][j][3], 0.03125f, bb.y);
            *(uint32_t*)(C + (size_t)row0 * E + col)       = pack_f16(x0, x1);
            *(uint32_t*)(C + (size_t)(row0 + 8) * E + col) = pack_f16(x2, x3);
        }
    }
}

// ---------------------------------------------------------------------------
// fp16 flash attention v10: as v9 (BKV=64, 3-stage ring, 1 barrier/chunk)
// plus IN-CHUNK SOFTWARE PIPELINING: K-frags double-buffered across S steps,
// V-frags double-buffered across PV blocks, so LDSM latency overlaps MMA.
// ---------------------------------------------------------------------------
#define ROWA 272
#define KV_TILE64 (64 * ROWA)            // 17408
#define KV_STAGE64 (2 * KV_TILE64)       // 34816 (K + V)
#define ATTN_SMEM (3 * KV_STAGE64)       // 104448
#define SSCALE_L2E 0.04508422002778545f
#define SBIAS_L2E  (-5.770780163555852f)

__global__ __launch_bounds__(128, 2) void attn_mma(float* __restrict__ out)
{
    const int qt  = blockIdx.x;
    const int h   = blockIdx.y;
    const int b   = blockIdx.z;
    const int tid = threadIdx.x;
    const int wid = tid >> 5;
    const int lane = tid & 31;
    const int m0 = wid * 16;

    extern __shared__ char smraw[];
    const uint32_t sb = smem_to_u32(smraw);

    const size_t qRow0 = (size_t)b * SQ + (size_t)qt * 64;

    const int aRow = lane & 15;
    const int aK   = (lane >> 4) << 3;
    const int bRow = (lane & 7) + ((lane >> 4) << 3);
    const int bK   = ((lane >> 3) & 1) << 3;
    const int vRow = (lane & 7) + (((lane >> 3) & 1) << 3);
    const int vCol = ((lane >> 4) & 1) << 3;

    // ---- stage Q into smem, pull fragments into registers ----
    uint32_t qh[8][4];
    {
#pragma unroll
        for (int t = 0; t < 8; t++) {
            int flat = tid + t * 128;
            int row  = flat >> 4;
            int ch   = flat & 15;
            uint32_t dst = sb + row * ROWA + ch * 16;
            const __half* src = g_qp + (qRow0 + row) * E + (size_t)h * HD + ch * 8;
            CP_ASYNC_16(dst, src);
        }
        CP_COMMIT();
        cp_wait<0>();
        __syncthreads();
#pragma unroll
        for (int step = 0; step < 8; step++) {
            uint32_t adr = sb + (m0 + aRow) * ROWA + (step * 16 + aK) * 2;
            LDMATRIX_X4(qh[step][0], qh[step][1], qh[step][2], qh[step][3], adr);
        }
        __syncthreads();
    }

    auto issue_kv = [&](int c, int s) {
        const size_t kvBase = (size_t)b * SKV + (size_t)c * 64;
#pragma unroll
        for (int t = 0; t < 16; t++) {
            int flat = tid + t * 128;
            int tile = flat >> 10;              // 0=K 1=V
            int idx  = flat & 1023;
            int row  = idx >> 4;
            int ch   = idx & 15;
            uint32_t dst = sb + s * KV_STAGE64 + tile * KV_TILE64 + row * ROWA + ch * 16;
            const __half* src = (tile == 0 ? g_kp : g_vp)
                + (kvBase + row) * E + (size_t)h * HD + ch * 8;
            CP_ASYNC_16(dst, src);
        }
        CP_COMMIT();
    };

    float o[16][4];
#pragma unroll
    for (int j = 0; j < 16; j++)
#pragma unroll
        for (int r = 0; r < 4; r++) o[j][r] = 0.f;
    float lsum0 = 0.f, lsum1 = 0.f;

    issue_kv(0, 0);
    issue_kv(1, 1);

    auto softmax_g = [&](float sf[8][4], int g, uint32_t pah[4]) {
        float p0 = exp2f(fmaf(sf[2 * g][0], SSCALE_L2E, SBIAS_L2E));
        float p1 = exp2f(fmaf(sf[2 * g][1], SSCALE_L2E, SBIAS_L2E));
        float p2 = exp2f(fmaf(sf[2 * g][2], SSCALE_L2E, SBIAS_L2E));
        float p3 = exp2f(fmaf(sf[2 * g][3], SSCALE_L2E, SBIAS_L2E));
        float p4 = exp2f(fmaf(sf[2 * g + 1][0], SSCALE_L2E, SBIAS_L2E));
        float p5 = exp2f(fmaf(sf[2 * g + 1][1], SSCALE_L2E, SBIAS_L2E));
        float p6 = exp2f(fmaf(sf[2 * g + 1][2], SSCALE_L2E, SBIAS_L2E));
        float p7 = exp2f(fmaf(sf[2 * g + 1][3], SSCALE_L2E, SBIAS_L2E));
        lsum0 += p0 + p1 + p4 + p5;
        lsum1 += p2 + p3 + p6 + p7;
        pah[0] = pack_f16(p0, p1);
        pah[1] = pack_f16(p2, p3);
        pah[2] = pack_f16(p4, p5);
        pah[3] = pack_f16(p6, p7);
    };

    const int NCH = SKV / 64;            // 32
    for (int c = 0; c < NCH; c++) {
        const int s = c % 3;
        if (c < NCH - 1) cp_wait<1>(); else cp_wait<0>();
        __syncthreads();
        if (c + 2 < NCH) issue_kv(c + 2, (c + 2) % 3);

        const uint32_t kB = sb + s * KV_STAGE64;
        const uint32_t vB = kB + KV_TILE64;

        // ---- S = Q K, K-frags double-buffered across steps ----
        float sf[8][4];
#pragma unroll
        for (int f = 0; f < 8; f++)
#pragma unroll
            for (int r = 0; r < 4; r++) sf[f][r] = 0.f;

        uint32_t bhb[2][4][4];
#pragma unroll
        for (int g = 0; g < 4; g++) {
            uint32_t ka = kB + (g * 16 + bRow) * ROWA + (0 + bK) * 2;
            LDMATRIX_X4(bhb[0][g][0], bhb[0][g][1], bhb[0][g][2], bhb[0][g][3], ka);
        }
#pragma unroll
        for (int step = 0; step < 8; step++) {
            const int cur = step & 1, nxt = cur ^ 1;
            if (step < 7) {
#pragma unroll
                for (int g = 0; g < 4; g++) {
                    uint32_t ka = kB + (g * 16 + bRow) * ROWA + ((step + 1) * 16 + bK) * 2;
                    LDMATRIX_X4(bhb[nxt][g][0], bhb[nxt][g][1],
                                bhb[nxt][g][2], bhb[nxt][g][3], ka);
                }
            }
#pragma unroll
            for (int g = 0; g < 4; g++) {
                MMA_F16(sf[2 * g],     qh[step], bhb[cur][g][0], bhb[cur][g][1]);
                MMA_F16(sf[2 * g + 1], qh[step], bhb[cur][g][2], bhb[cur][g][3]);
            }
        }

        // ---- softmax + PV, V-frags double-buffered across the 16 blocks ----
        uint32_t pa[4][4];
        softmax_g(sf, 0, pa[0]);
        softmax_g(sf, 1, pa[1]);

        uint32_t vhb[2][2][4];
        // preload block 0 (kk=0, np=0)
#pragma unroll
        for (int u = 0; u < 2; u++) {
            uint32_t va = vB + (0 * 16 + vRow) * ROWA + ((0 * 2 + u) * 16 + vCol) * 2;
            LDMATRIX_X4_T(vhb[0][u][0], vhb[0][u][1], vhb[0][u][2], vhb[0][u][3], va);
        }
#pragma unroll
        for (int blk = 0; blk < 16; blk++) {
            const int cur = blk & 1, nxt = cur ^ 1;
            if (blk < 15) {
                const int kkn = (blk + 1) >> 2, npn = (blk + 1) & 3;
#pragma unroll
                for (int u = 0; u < 2; u++) {
                    uint32_t va = vB + (kkn * 16 + vRow) * ROWA + ((npn * 2 + u) * 16 + vCol) * 2;
                    LDMATRIX_X4_T(vhb[nxt][u][0], vhb[nxt][u][1],
                                  vhb[nxt][u][2], vhb[nxt][u][3], va);
                }
            }
            // deferred softmax for kk=2,3 overlaps the in-flight loads/MMAs
            if (blk == 2) softmax_g(sf, 2, pa[2]);
            if (blk == 6) softmax_g(sf, 3, pa[3]);
            const int kk = blk >> 2, np = blk & 3;
            MMA_F16(o[np * 4 + 0], pa[kk], vhb[cur][0][0], vhb[cur][0][1]);
            MMA_F16(o[np * 4 + 1], pa[kk], vhb[cur][0][2], vhb[cur][0][3]);
            MMA_F16(o[np * 4 + 2], pa[kk], vhb[cur][1][0], vhb[cur][1][1]);
            MMA_F16(o[np * 4 + 3], pa[kk], vhb[cur][1][2], vhb[cur][1][3]);
        }
        // no trailing barrier (3-stage ring)
    }

    // ---- reduce l, normalize, store ----
    lsum0 += __shfl_xor_sync(0xffffffffu, lsum0, 1);
    lsum0 += __shfl_xor_sync(0xffffffffu, lsum0, 2);
    lsum1 += __shfl_xor_sync(0xffffffffu, lsum1, 1);
    lsum1 += __shfl_xor_sync(0xffffffffu, lsum1, 2);
    const float inv0 = 1.f / lsum0;
    const float inv1 = 1.f / lsum1;

    const int rw = lane >> 2;
    const int cw = (lane & 3) * 2;
    const size_t row0 = qRow0 + m0 + rw;
#pragma unroll
    for (int j = 0; j < 16; j++) {
        int col = h * HD + j * 8 + cw;
        float2 w0 = {o[j][0] * inv0, o[j][1] * inv0};
        float2 w1 = {o[j][2] * inv1, o[j][3] * inv1};
        *(float2*)(out + row0 * E + col)       = w0;
        *(float2*)(out + (row0 + 8) * E + col) = w1;
    }
}

// ---------------------------------------------------------------------------
// Launch
// ---------------------------------------------------------------------------
extern "C" void kernel_launch(void* const* d_in, const int* in_sizes, int n_in,
                              void* d_out, int out_size)
{
    const float* q  = (const float*)d_in[0];
    const float* v  = (const float*)d_in[1];
    const float* Wq = (const float*)d_in[2];
    const float* bq = (const float*)d_in[3];
    const float* Wk = (const float*)d_in[4];
    const float* bk = (const float*)d_in[5];
    const float* Wv = (const float*)d_in[6];
    const float* bv = (const float*)d_in[7];
    float* out = (float*)d_out;

    conv_act<<<dim3(8192, 2), 256>>>(q, v);
    conv_w<<<dim3(32, 32, 3), dim3(32, 8)>>>(Wq, Wk, Wv);

    int gsmem = 3 * G_STAGE3;   // 110592
    cudaFuncSetAttribute(gemm_mma, cudaFuncAttributeMaxDynamicSharedMemorySize, gsmem);
    gemm_mma<<<dim3(E / 128, (BATCH * SQ) / 128, 3), 256, gsmem>>>(bq, bk, bv);

    cudaFuncSetAttribute(attn_mma, cudaFuncAttributeMaxDynamicSharedMemorySize, ATTN_SMEM);
    attn_mma<<<dim3(SQ / 64, H, BATCH), 128, ATTN_SMEM>>>(out);
}